// round 10
// baseline (speedup 1.0000x reference)
#include <cuda_runtime.h>
#include <cuda_fp16.h>
#include <stdint.h>
#include <math.h>

#define SEQ   8192
#define INP   512
#define HYP   1024
#define HIDN  4096
#define CHUNK 128
#define NCHUNK (SEQ/CHUNK)   // 64

// ---------------- scratch (static __device__, no allocations) ----------------
__device__ __half g_xh  [SEQ*INP];
__device__ __half g_h1h [SEQ*HYP];
__device__ __half g_h2h [SEQ*HYP];
__device__ __half g_h3h [SEQ*HYP];
__device__ __half g_Gh  [SEQ*HIDN];
__device__ __half g_Bh  [SEQ*HIDN];
__device__ __half g_w15 [(HYP+HIDN)*INP];    // [w_in ; w2] rows, K=512
__device__ __half g_wI  [2*HYP*HYP];         // interleaved wg0/wg0g
__device__ __half g_wshh[HYP*HYP];
__device__ __half g_whh [HIDN*HYP];
__device__ float g_Ac[NCHUNK*HIDN];
__device__ float g_Bc[NCHUNK*HIDN];
__device__ float g_Gb[(NCHUNK+1)*HIDN];

// ---------------- PTX helpers (sm_100-portable only) --------------------------
__device__ __forceinline__ uint32_t smem_u32(const void* p) {
    uint32_t a;
    asm("{ .reg .u64 t; cvta.to.shared.u64 t, %1; cvt.u32.u64 %0, t; }" : "=r"(a) : "l"(p));
    return a;
}
__device__ __forceinline__ void cp16(uint32_t dst, const void* src) {
    asm volatile("cp.async.cg.shared.global [%0], [%1], 16;" :: "r"(dst), "l"(src));
}
__device__ __forceinline__ void cp_commit() { asm volatile("cp.async.commit_group;"); }
template <int N> __device__ __forceinline__ void cp_wait() {
    asm volatile("cp.async.wait_group %0;" :: "n"(N));
}
__device__ __forceinline__ void ldm4(uint32_t* r, uint32_t addr) {
    asm volatile("ldmatrix.sync.aligned.m8n8.x4.shared.b16 {%0,%1,%2,%3}, [%4];"
                 : "=r"(r[0]), "=r"(r[1]), "=r"(r[2]), "=r"(r[3]) : "r"(addr));
}
__device__ __forceinline__ void mma16816(float* d, const uint32_t* a, const uint32_t* b) {
    asm volatile(
        "mma.sync.aligned.m16n8k16.row.col.f32.f16.f16.f32 "
        "{%0,%1,%2,%3}, {%4,%5,%6,%7}, {%8,%9}, {%0,%1,%2,%3};"
        : "+f"(d[0]), "+f"(d[1]), "+f"(d[2]), "+f"(d[3])
        : "r"(a[0]), "r"(a[1]), "r"(a[2]), "r"(a[3]), "r"(b[0]), "r"(b[1]));
}

// ---------------- fp16 GEMM: C[M,N] = A[M,K] @ W[N,K]^T + bias ----------------
// 128x128 tile, BK=64, XOR-swizzled 128B smem rows, 3-stage cp.async ring,
// register-double-buffered ldmatrix fragments (prefetch distance = 1 mf step).
#define BM 128
#define BN 128
#define BKE 64
#define OPER 16384
#define STAGE (2*OPER)           // 32 KB
#define NSTAGE 3
#define SMEM_DYN (NSTAGE*STAGE)  // 98304 B

#define M_PLAIN 0
#define M_GATE  1
#define M_SILU  2
#define M_PAIR  3   // interleaved value/gate cols -> v*sigm(g); bias/bias2 = bg0/bg0g
#define M_DUAL  4   // bn<HYP -> Ch(+bias, N=HYP); else -> Ch2(+bias2, N=HIDN)

__device__ __forceinline__ float sigm(float x) { return 1.f / (1.f + expf(-x)); }

__global__ __launch_bounds__(256, 2)
void gemm_f16(const __half* __restrict__ A, const __half* __restrict__ W,
              const float* __restrict__ bias, const float* __restrict__ bias2,
              const __half* __restrict__ aux,
              int N, int K, int Nout, int mode,
              __half* __restrict__ Ch, __half* __restrict__ Ch2)
{
    extern __shared__ char dsmem[];
    const int tid = threadIdx.x, lane = tid & 31, wid = tid >> 5;
    const int warp_m = wid >> 2, warp_n = wid & 3;
    const int bm = blockIdx.y * BM, bn = blockIdx.x * BN;
    const uint32_t sbase = smem_u32(dsmem);

    float acc[4][4][4];
#pragma unroll
    for (int i = 0; i < 4; i++)
#pragma unroll
        for (int j = 0; j < 4; j++)
#pragma unroll
            for (int q = 0; q < 4; q++) acc[i][j][q] = 0.f;

    uint32_t arow[4], asw[4], brow[2], bsw[2];
    const uint32_t ksA = (lane >> 4) & 1;
    const uint32_t ksB = (lane >> 3) & 1;
    {
        int rA = (lane & 7) + ((lane >> 3) & 1) * 8;
#pragma unroll
        for (int mf = 0; mf < 4; mf++) {
            int r = warp_m * 64 + mf * 16 + rA;
            arow[mf] = (uint32_t)(r * 128);
            asw[mf]  = (uint32_t)(r & 7);
        }
        int rB = (lane & 7) + ((lane >> 4) & 1) * 8;
#pragma unroll
        for (int g = 0; g < 2; g++) {
            int r = warp_n * 32 + g * 16 + rB;
            brow[g] = (uint32_t)(r * 128);
            bsw[g]  = (uint32_t)(r & 7);
        }
    }

    const int spt = K / BKE;

    auto load_stage = [&](int k0, int buf) {
        uint32_t dA = sbase + (uint32_t)buf * STAGE;
        uint32_t dB = dA + OPER;
#pragma unroll
        for (int i = 0; i < 4; i++) {
            int c = i * 256 + tid;
            int r = c >> 3, seg = c & 7;
            uint32_t o = (uint32_t)(r * 128 + ((seg ^ (r & 7)) << 4));
            cp16(dA + o, A + (size_t)(bm + r) * K + k0 + seg * 8);
            cp16(dB + o, W + (size_t)(bn + r) * K + k0 + seg * 8);
        }
    };

    load_stage(0, 0);  cp_commit();
    load_stage(BKE, 1); cp_commit();

    for (int s = 0; s < spt; s++) {
        const int buf = s % NSTAGE;
        if (s < spt - 1) cp_wait<1>(); else cp_wait<0>();
        __syncthreads();
        if (s + 2 < spt) { load_stage((s + 2) * BKE, (s + 2) % NSTAGE); cp_commit(); }

        const uint32_t sA = sbase + (uint32_t)buf * STAGE;
        const uint32_t sB = sA + OPER;

        // register-double-buffered fragments, prefetch distance = 1 mf step
        uint32_t ar[2][4], br[2][8];
        ldm4(br[0],     sB + brow[0] + ((0u + ksB) ^ bsw[0]) * 16);
        ldm4(br[0] + 4, sB + brow[1] + ((0u + ksB) ^ bsw[1]) * 16);
        ldm4(ar[0],     sA + arow[0] + ((0u + ksA) ^ asw[0]) * 16);

#pragma unroll
        for (int ks = 0; ks < 4; ks++) {
#pragma unroll
            for (int mf = 0; mf < 4; mf++) {
                const int cur  = (ks * 4 + mf) & 1;
                const int bcur = ks & 1;
                if (mf < 3) {
                    ldm4(ar[cur ^ 1],
                         sA + arow[mf + 1] + (((uint32_t)(ks * 2) + ksA) ^ asw[mf + 1]) * 16);
                } else if (ks < 3) {
                    ldm4(br[bcur ^ 1],
                         sB + brow[0] + (((uint32_t)((ks + 1) * 2) + ksB) ^ bsw[0]) * 16);
                    ldm4(br[bcur ^ 1] + 4,
                         sB + brow[1] + (((uint32_t)((ks + 1) * 2) + ksB) ^ bsw[1]) * 16);
                    ldm4(ar[cur ^ 1],
                         sA + arow[0] + (((uint32_t)((ks + 1) * 2) + ksA) ^ asw[0]) * 16);
                }
#pragma unroll
                for (int nf = 0; nf < 4; nf++)
                    mma16816(acc[mf][nf], ar[cur], br[bcur] + nf * 2);
            }
        }
    }

    // ------------- fused epilogue -------------
    __half* outp = Ch;
    const float* biasp = bias;
    int Nloc = Nout, nbase = bn;
    if (mode == M_DUAL && bn >= HYP) {
        outp = Ch2; biasp = bias2; Nloc = HIDN; nbase = bn - HYP;
    }

    float2 bv[4];
#pragma unroll
    for (int nf = 0; nf < 4; nf++) {
        int nloc = nbase + warp_n * 32 + nf * 8 + (lane & 3) * 2;
        if (mode == M_PAIR) {
            bv[nf].x = bias[nloc >> 1];
            bv[nf].y = bias2[nloc >> 1];
        } else {
            bv[nf] = *(const float2*)&biasp[nloc];
        }
    }

#pragma unroll
    for (int mf = 0; mf < 4; mf++) {
#pragma unroll
        for (int h = 0; h < 2; h++) {
            const int row = bm + warp_m * 64 + mf * 16 + (lane >> 2) + h * 8;
#pragma unroll
            for (int nf = 0; nf < 4; nf++) {
                const int nloc = nbase + warp_n * 32 + nf * 8 + (lane & 3) * 2;
                float v0 = acc[mf][nf][h * 2 + 0] + bv[nf].x;
                float v1 = acc[mf][nf][h * 2 + 1] + bv[nf].y;
                if (mode == M_PAIR) {
                    outp[(size_t)row * Nout + (nloc >> 1)] = __float2half(v0 * sigm(v1));
                } else {
                    if (mode == M_GATE) {
                        __half2 g = *(const __half2*)&aux[(size_t)row * N + nloc];
                        v0 *= sigm(__half2float(g.x));
                        v1 *= sigm(__half2float(g.y));
                    } else if (mode == M_SILU) {
                        v0 *= sigm(v0); v1 *= sigm(v1);
                    }
                    __half2 o; o.x = __float2half(v0); o.y = __float2half(v1);
                    *(__half2*)&outp[(size_t)row * Nloc + nloc] = o;
                }
            }
        }
    }
}

// ---------------- mega conversion kernel (one launch) --------------------------
#define C0 (SEQ*INP)
#define C1 (C0 + HYP*INP)
#define C2 (C1 + HIDN*INP)
#define C3 (C2 + 2*HYP*HYP)
#define C4 (C3 + HYP*HYP)
#define C5 (C4 + HIDN*HYP)
#define CVT_THREADS ((C5)/4)

__device__ __forceinline__ void cvt4(const float* s, __half* d) {
    float4 v = *(const float4*)s;
    __half2 a; a.x = __float2half(v.x); a.y = __float2half(v.y);
    __half2 b; b.x = __float2half(v.z); b.y = __float2half(v.w);
    *(__half2*)d       = a;
    *(__half2*)(d + 2) = b;
}

__global__ void mega_cvt(const float* __restrict__ x,    const float* __restrict__ w_in,
                         const float* __restrict__ w2,   const float* __restrict__ wg0,
                         const float* __restrict__ wg0g, const float* __restrict__ wg_sh,
                         const float* __restrict__ w_h,
                         __half* __restrict__ xh, __half* __restrict__ w15,
                         __half* __restrict__ wI, __half* __restrict__ wshh,
                         __half* __restrict__ whh)
{
    int i = (blockIdx.x * blockDim.x + threadIdx.x) * 4;
    if (i < C0) {
        cvt4(x + i, xh + i);
    } else if (i < C1) {
        int j = i - C0; cvt4(w_in + j, w15 + j);
    } else if (i < C2) {
        int j = i - C1; cvt4(w2 + j, w15 + HYP*INP + j);
    } else if (i < C3) {
        int j = i - C2;
        int r = j >> 10, k = j & (HYP - 1);
        const float* s = (r & 1) ? wg0g : wg0;
        cvt4(s + ((size_t)(r >> 1) << 10) + k, wI + j);
    } else if (i < C4) {
        int j = i - C3; cvt4(wg_sh + j, wshh + j);
    } else if (i < C5) {
        int j = i - C4; cvt4(w_h + j, whh + j);
    }
}

// ---------------- rotated-frame relu scan (fp16 B) ----------------------------
__global__ void scan_pass1(const __half* __restrict__ B,
                           float* __restrict__ Ac, float* __restrict__ Bc)
{
    int t    = blockIdx.x * blockDim.x + threadIdx.x;
    int lane = t & (HIDN - 1);
    int chnk = t >> 12;
    float Aa = -1e30f, Ss = 0.f;
    int base = chnk * CHUNK;
#pragma unroll 8
    for (int i = 0; i < CHUNK; i++) {
        int row = base + i;
        float b = __half2float(B[(size_t)row * HIDN + ((lane + row) & (HIDN - 1))]);
        Aa = fmaxf(0.f, b + Aa);
        Ss += b;
    }
    Ac[t] = Aa; Bc[t] = Ss;
}

__global__ void scan_combine(const float* __restrict__ hidden,
                             const float* __restrict__ Ac, const float* __restrict__ Bc,
                             float* __restrict__ Gb)
{
    int lane = blockIdx.x * blockDim.x + threadIdx.x;
    float gv = hidden[(lane - 1) & (HIDN - 1)];
    Gb[lane] = gv;
    for (int c = 0; c < NCHUNK; c++) {
        gv = fmaxf(Ac[c * HIDN + lane], Bc[c * HIDN + lane] + gv);
        Gb[(c + 1) * HIDN + lane] = gv;
    }
}

__global__ void scan_pass2(const __half* __restrict__ B, const float* __restrict__ Gb,
                           float* __restrict__ out, float* __restrict__ hlast, int write_h)
{
    int t    = blockIdx.x * blockDim.x + threadIdx.x;
    int lane = t & (HIDN - 1);
    int chnk = t >> 12;
    float gv = Gb[chnk * HIDN + lane];
    int base = chnk * CHUNK;
#pragma unroll 4
    for (int i = 0; i < CHUNK; i++) {
        int row = base + i;
        int col = (lane + row) & (HIDN - 1);
        gv = fmaxf(0.f, __half2float(B[(size_t)row * HIDN + col]) + gv);
        out[(size_t)row * HIDN + col] = gv;
    }
    if (write_h && chnk == NCHUNK - 1)
        hlast[(lane - 1) & (HIDN - 1)] = gv;
}

// ---------------- launch ------------------------------------------------------
extern "C" void kernel_launch(void* const* d_in, const int* in_sizes, int n_in,
                              void* d_out, int out_size)
{
    const float* x      = (const float*)d_in[0];
    const float* hidden = (const float*)d_in[1];
    const float* w_in   = (const float*)d_in[2];
    const float* b_in   = (const float*)d_in[3];
    const float* wg0    = (const float*)d_in[4];
    const float* bg0    = (const float*)d_in[5];
    const float* wg0g   = (const float*)d_in[6];
    const float* bg0g   = (const float*)d_in[7];
    const float* wg_sh  = (const float*)d_in[8];
    const float* bg_sh  = (const float*)d_in[9];
    const float* w_h    = (const float*)d_in[10];
    const float* b_h    = (const float*)d_in[11];
    const float* w2     = (const float*)d_in[12];
    const float* b2     = (const float*)d_in[13];

    float* out   = (float*)d_out;
    float* hlast = out + (size_t)SEQ * HIDN;
    int write_h  = (out_size >= SEQ * HIDN + HIDN) ? 1 : 0;

    cudaFuncSetAttribute(gemm_f16, cudaFuncAttributeMaxDynamicSharedMemorySize, SMEM_DYN);

    __half *xh, *h1h, *h2h, *h3h, *Gh, *Bh, *w15, *wI, *wshh, *whh;
    float *Ac, *Bc, *Gb;
    cudaGetSymbolAddress((void**)&xh,  g_xh);
    cudaGetSymbolAddress((void**)&h1h, g_h1h);
    cudaGetSymbolAddress((void**)&h2h, g_h2h);
    cudaGetSymbolAddress((void**)&h3h, g_h3h);
    cudaGetSymbolAddress((void**)&Gh,  g_Gh);
    cudaGetSymbolAddress((void**)&Bh,  g_Bh);
    cudaGetSymbolAddress((void**)&w15,  g_w15);
    cudaGetSymbolAddress((void**)&wI,   g_wI);
    cudaGetSymbolAddress((void**)&wshh, g_wshh);
    cudaGetSymbolAddress((void**)&whh,  g_whh);
    cudaGetSymbolAddress((void**)&Ac, g_Ac);
    cudaGetSymbolAddress((void**)&Bc, g_Bc);
    cudaGetSymbolAddress((void**)&Gb, g_Gb);

    mega_cvt<<<(CVT_THREADS + 255)/256, 256>>>(x, w_in, w2, wg0, wg0g, wg_sh, w_h,
                                               xh, w15, wI, wshh, whh);

    const dim3 gDual((HYP + HIDN) / BN, SEQ / BM);   // 40 x 64
    const dim3 gPair(2*HYP / BN,        SEQ / BM);   // 16 x 64
    const dim3 gHyp (HYP / BN,          SEQ / BM);   //  8 x 64
    const dim3 gHid (HIDN / BN,         SEQ / BM);   // 32 x 64

    // [h1 ; G] = x @ [w_in ; w2]^T + [b_in ; b2]
    gemm_f16<<<gDual, 256, SMEM_DYN>>>(xh, w15, b_in, b2, nullptr,
                                       HYP + HIDN, INP, HYP, M_DUAL, h1h, Gh);
    // h2 = (h1 @ wg0^T + bg0) * sigmoid(h1 @ wg0g^T + bg0g)
    gemm_f16<<<gPair, 256, SMEM_DYN>>>(h1h, wI, bg0, bg0g, nullptr,
                                       2*HYP, HYP, HYP, M_PAIR, h2h, nullptr);
    // h3 = silu(h2 @ wg_sh^T + bg_sh)
    gemm_f16<<<gHyp, 256, SMEM_DYN>>>(h2h, wshh, bg_sh, nullptr, nullptr,
                                      HYP, HYP, HYP, M_SILU, h3h, nullptr);
    // B = (h3 @ w_h^T + b_h) * sigmoid(G)
    gemm_f16<<<gHid, 256, SMEM_DYN>>>(h3h, whh, b_h, nullptr, Gh,
                                      HIDN, HYP, HIDN, M_GATE, Bh, nullptr);

    // chunked rotated-frame scan
    scan_pass1 <<<NCHUNK*HIDN/256, 256>>>(Bh, Ac, Bc);
    scan_combine<<<HIDN/256, 256>>>(hidden, Ac, Bc, Gb);
    scan_pass2 <<<NCHUNK*HIDN/256, 256>>>(Bh, Gb, out, hlast, write_h);
}